// round 16
// baseline (speedup 1.0000x reference)
#include <cuda_runtime.h>
#include <cstdint>
#include <cstddef>

// Adaptive separable convolution (SepConv), sm_103a.
// out[b,c,y,w] = sum_i sum_j inp[b,c,y+i,w+j] * V[b,i,y,w] * Hz[b,j,y,w]
//
// Round-16 = Round-3 champion (70.6us) verbatim, plus the only two isolated
// nonnegative micro-deltas:
//  * depth-2 V register ring (R12 mechanism, isolated here): V[i+1] is
//    resident a full comp block before use.
//  * float4 patch fill (half the fill instructions / L1 wavefronts).
// Everything else byte-identical to R3: FFMA2 packed math, 4 px/thread,
// one channel per CTA, TILE 128x4, 128-thread CTAs, 3 CTAs/SM, 2 weight
// phases (pairs k=0..13 / 14..26), float4 smem loads + pk2 repack.

#define KF   51
#define BB   2
#define CC   3
#define HH   256
#define WW   256
#define HW   (HH * WW)            // 65536
#define IN_H (HH + KF - 1)        // 306
#define IN_W (WW + KF - 1)        // 306

#define TILE_W 128
#define TILE_H 4
#define PATCH_H (TILE_H + KF - 1) // 54
#define PATCH_W (TILE_W + KF - 1) // 178
#define PATCH_WP 180              // padded row: 720B, 16B-aligned

#define NTHREADS 128              // 4 warps, one output row each

__device__ __forceinline__ uint64_t pk2(float lo, float hi) {
    uint64_t r;
    asm("mov.b64 %0, {%1,%2};" : "=l"(r) : "f"(lo), "f"(hi));
    return r;
}
__device__ __forceinline__ void ffma2(uint64_t& acc, uint64_t a, uint64_t b) {
    asm("fma.rn.f32x2 %0, %1, %2, %0;" : "+l"(acc) : "l"(a), "l"(b));
}
__device__ __forceinline__ float hadd2(uint64_t p) {
    float lo, hi;
    asm("mov.b64 {%0,%1}, %2;" : "=f"(lo), "=f"(hi) : "l"(p));
    return lo + hi;
}

__global__ void __launch_bounds__(NTHREADS, 3)
sepconv_kernel(const float* __restrict__ inp,
               const float* __restrict__ ver,
               const float* __restrict__ hor,
               float* __restrict__ out)
{
    __shared__ __align__(16) float sm[PATCH_H][PATCH_WP];

    const int bx = blockIdx.x;            // 0..1   tile col
    const int by = blockIdx.y;            // 0..63  tile row
    const int bc = blockIdx.z;            // 0..5   (b, c) fused
    const int b  = bc / CC;
    const int c  = bc - b * CC;
    const int x0 = bx * TILE_W;
    const int y0 = by * TILE_H;

    const int tid  = threadIdx.x;
    const int lane = tid & 31;
    const int wy   = tid >> 5;            // warp id == row within tile
    const int y    = y0 + wy;             // output row
    const int w0   = x0 + 4 * lane;       // first of 4 output cols

    const float* Hb = hor + ((size_t)b * KF * HW) + (size_t)y * WW + w0;
    const float* Vb = ver + ((size_t)b * KF * HW) + (size_t)y * WW + w0;

    // horizontal weight fetch for pixel p, tap j (compile-time predicated pad)
    auto hz = [&](int p, int j) -> float {
        return (j >= 0 && j < KF) ? Hb[(size_t)j * HW + p] : 0.0f;
    };

    // ---- single patch fill for this CTA's channel (float4 main + float2 tail)
    {
        const float* src = inp + ((size_t)(b * CC + c) * IN_H + y0) * IN_W + x0;
        // 178 floats per row = 44 float4 + 1 float2
        for (int t = tid; t < PATCH_H * 44; t += NTHREADS) {
            int r  = t / 44;
            int c4 = t - r * 44;
            // src rows are not 16B-aligned relative to x0; use two float2s
            const float* s = src + (size_t)r * IN_W + 4 * c4;
            float2 v0 = *(const float2*)(s);
            float2 v1 = *(const float2*)(s + 2);
            *(float2*)(&sm[r][4 * c4])     = v0;
            *(float2*)(&sm[r][4 * c4 + 2]) = v1;
        }
        if (tid < PATCH_H) {  // tail floats 176,177
            float2 v = *(const float2*)(src + (size_t)tid * IN_W + 176);
            *(float2*)(&sm[tid][176]) = v;
        }
    }

    float res0, res1, res2, res3;

    // ================= PHASE A : pairs k = 0..13 (taps j <= 28) =============
    {
        uint64_t wa0[14], wa1[14], wa2[13], wa3[13];
#pragma unroll
        for (int k = 0; k < 14; ++k) {
            wa0[k] = pk2(hz(0, 2 * k),     hz(0, 2 * k + 1));
            wa1[k] = pk2(hz(1, 2 * k - 1), hz(1, 2 * k));
        }
#pragma unroll
        for (int k = 1; k < 14; ++k) {
            wa2[k - 1] = pk2(hz(2, 2 * k - 2), hz(2, 2 * k - 1));
            wa3[k - 1] = pk2(hz(3, 2 * k - 3), hz(3, 2 * k - 2));
        }

        __syncthreads();   // patch visible before compute

        uint64_t o0 = 0, o1 = 0, o2 = 0, o3 = 0;
        float4 va = *(const float4*)Vb;                 // V row 0
        float4 vb = *(const float4*)(Vb + HW);          // V row 1
#pragma unroll 1
        for (int i = 0; i < KF; ++i) {
            const float4* srow4 = (const float4*)(&sm[wy + i][0]);
            uint64_t a0 = 0, a1 = 0, a2 = 0, a3 = 0;
#pragma unroll
            for (int t = 0; t < 7; ++t) {
                float4 s4 = srow4[lane + t];
                uint64_t q0 = pk2(s4.x, s4.y);   // pair k = 2t
                uint64_t q1 = pk2(s4.z, s4.w);   // pair k = 2t+1
                int k0 = 2 * t, k1 = 2 * t + 1;
                ffma2(a0, wa0[k0], q0);
                ffma2(a1, wa1[k0], q0);
                if (k0 >= 1) { ffma2(a2, wa2[k0 - 1], q0); ffma2(a3, wa3[k0 - 1], q0); }
                ffma2(a0, wa0[k1], q1);
                ffma2(a1, wa1[k1], q1);
                ffma2(a2, wa2[k1 - 1], q1);
                ffma2(a3, wa3[k1 - 1], q1);
            }
            ffma2(o0, pk2(va.x, va.x), a0);
            ffma2(o1, pk2(va.y, va.y), a1);
            ffma2(o2, pk2(va.z, va.z), a2);
            ffma2(o3, pk2(va.w, va.w), a3);
            // advance depth-2 V ring (clamped)
            va = vb;
            int nxt = (i + 2 < KF) ? (i + 2) : (KF - 1);
            vb = *(const float4*)(Vb + (size_t)nxt * HW);
        }
        res0 = hadd2(o0);
        res1 = hadd2(o1);
        res2 = hadd2(o2);
        res3 = hadd2(o3);
    }

    __syncthreads();   // fence: keep phase-B weight loads below phase A

    // ================= PHASE B : pairs k = 14..26 (taps j >= 25) ============
    {
        uint64_t wb0[12], wb1[12], wb2[13], wb3[13];
#pragma unroll
        for (int k = 14; k < 26; ++k) {
            wb0[k - 14] = pk2(hz(0, 2 * k),     hz(0, 2 * k + 1)); // k=25 -> pad
            wb1[k - 14] = pk2(hz(1, 2 * k - 1), hz(1, 2 * k));
        }
#pragma unroll
        for (int k = 14; k < 27; ++k) {
            wb2[k - 14] = pk2(hz(2, 2 * k - 2), hz(2, 2 * k - 1)); // k=26 -> pad
            wb3[k - 14] = pk2(hz(3, 2 * k - 3), hz(3, 2 * k - 2));
        }

        uint64_t o0 = 0, o1 = 0, o2 = 0, o3 = 0;
        float4 va = *(const float4*)Vb;                 // V row 0
        float4 vb = *(const float4*)(Vb + HW);          // V row 1
#pragma unroll 1
        for (int i = 0; i < KF; ++i) {
            const float* srow = &sm[wy + i][0];
            const float4* srow4 = (const float4*)srow;
            uint64_t a0 = 0, a1 = 0, a2 = 0, a3 = 0;
#pragma unroll
            for (int t = 0; t < 6; ++t) {
                float4 s4 = srow4[lane + 7 + t];          // floats 28..51
                uint64_t q0 = pk2(s4.x, s4.y);            // pair k = 14+2t
                uint64_t q1 = pk2(s4.z, s4.w);            // pair k = 15+2t
                int k0 = 2 * t, k1 = 2 * t + 1;           // rel index
                ffma2(a0, wb0[k0], q0);
                ffma2(a1, wb1[k0], q0);
                ffma2(a2, wb2[k0], q0);
                ffma2(a3, wb3[k0], q0);
                ffma2(a0, wb0[k1], q1);
                ffma2(a1, wb1[k1], q1);
                ffma2(a2, wb2[k1], q1);
                ffma2(a3, wb3[k1], q1);
            }
            {   // tail pair k = 26 (floats 52,53): pixels 2,3 only
                float2 s2 = *(const float2*)(srow + 4 * lane + 52);
                uint64_t q = pk2(s2.x, s2.y);
                ffma2(a2, wb2[12], q);
                ffma2(a3, wb3[12], q);
            }
            ffma2(o0, pk2(va.x, va.x), a0);
            ffma2(o1, pk2(va.y, va.y), a1);
            ffma2(o2, pk2(va.z, va.z), a2);
            ffma2(o3, pk2(va.w, va.w), a3);
            va = vb;
            int nxt = (i + 2 < KF) ? (i + 2) : (KF - 1);
            vb = *(const float4*)(Vb + (size_t)nxt * HW);
        }
        res0 += hadd2(o0);
        res1 += hadd2(o1);
        res2 += hadd2(o2);
        res3 += hadd2(o3);
    }

    // ---- write out ----
    float* o = out + ((size_t)(b * CC + c) * HH + y) * WW + w0;
    *(float4*)o = make_float4(res0, res1, res2, res3);
}

extern "C" void kernel_launch(void* const* d_in, const int* in_sizes, int n_in,
                              void* d_out, int out_size)
{
    (void)in_sizes; (void)n_in; (void)out_size;
    const float* inp = (const float*)d_in[0];   // [B, C, 306, 306]
    const float* ver = (const float*)d_in[1];   // [B, 51, 256, 256]
    const float* hor = (const float*)d_in[2];   // [B, 51, 256, 256]
    float*       out = (float*)d_out;           // [B, C, 256, 256]

    dim3 grid(WW / TILE_W, HH / TILE_H, BB * CC);   // (2, 64, 6) = 768 blocks
    dim3 block(NTHREADS);
    sepconv_kernel<<<grid, block>>>(inp, ver, hor, out);
}

// round 17
// speedup vs baseline: 1.0350x; 1.0350x over previous
#include <cuda_runtime.h>
#include <cstdint>
#include <cstddef>

// Adaptive separable convolution (SepConv), sm_103a.  FINAL (= Round-3).
// out[b,c,y,w] = sum_i sum_j inp[b,c,y+i,w+j] * V[b,i,y,w] * Hz[b,j,y,w]
//
// Champion configuration (best of 16 measured variants, 70.6us):
//  * FFMA2 (fma.rn.f32x2) packed math -- 2 lane-FMAs/instr, rt_SMSP=2
//    (confirmed on HW R2-R15): fp32 port floor halved vs scalar FFMA.
//  * 4 adjacent output pixels per thread -> each smem byte feeds 4 FMAs
//    (1 B/FMA crossbar intensity); dense 16B-aligned float4 smem loads are
//    conflict-free (16B lane stride).
//  * One channel per CTA (grid z = B*C), TILE 128x4, 128-thread CTAs,
//    3 CTAs/SM (162 regs; RF exactly full at 12 warps/SM).
//  * 2 weight phases (tap-pairs k=0..13 / 14..26) bound live packed-weight
//    registers to ~108 per phase; phases share one patch fill.
// Measured plateau: every occupancy / prefetch / pipeline / instruction-count
// mutation of this schedule landed 0.5-5us slower (R4-R16).

#define KF   51
#define BB   2
#define CC   3
#define HH   256
#define WW   256
#define HW   (HH * WW)            // 65536
#define IN_H (HH + KF - 1)        // 306
#define IN_W (WW + KF - 1)        // 306

#define TILE_W 128
#define TILE_H 4
#define PATCH_H (TILE_H + KF - 1) // 54
#define PATCH_W (TILE_W + KF - 1) // 178
#define PATCH_WP 180              // padded row: 720B, 16B-aligned

#define NTHREADS 128              // 4 warps, one output row each

__device__ __forceinline__ uint64_t pk2(float lo, float hi) {
    uint64_t r;
    asm("mov.b64 %0, {%1,%2};" : "=l"(r) : "f"(lo), "f"(hi));
    return r;
}
__device__ __forceinline__ void ffma2(uint64_t& acc, uint64_t a, uint64_t b) {
    asm("fma.rn.f32x2 %0, %1, %2, %0;" : "+l"(acc) : "l"(a), "l"(b));
}
__device__ __forceinline__ float hadd2(uint64_t p) {
    float lo, hi;
    asm("mov.b64 {%0,%1}, %2;" : "=f"(lo), "=f"(hi) : "l"(p));
    return lo + hi;
}

__global__ void __launch_bounds__(NTHREADS, 3)
sepconv_kernel(const float* __restrict__ inp,
               const float* __restrict__ ver,
               const float* __restrict__ hor,
               float* __restrict__ out)
{
    __shared__ __align__(16) float sm[PATCH_H][PATCH_WP];

    const int bx = blockIdx.x;            // 0..1   tile col
    const int by = blockIdx.y;            // 0..63  tile row
    const int bc = blockIdx.z;            // 0..5   (b, c) fused
    const int b  = bc / CC;
    const int c  = bc - b * CC;
    const int x0 = bx * TILE_W;
    const int y0 = by * TILE_H;

    const int tid  = threadIdx.x;
    const int lane = tid & 31;
    const int wy   = tid >> 5;            // warp id == row within tile
    const int y    = y0 + wy;             // output row
    const int w0   = x0 + 4 * lane;       // first of 4 output cols

    const float* Hb = hor + ((size_t)b * KF * HW) + (size_t)y * WW + w0;
    const float* Vb = ver + ((size_t)b * KF * HW) + (size_t)y * WW + w0;

    // horizontal weight fetch for pixel p, tap j (compile-time predicated pad)
    auto hz = [&](int p, int j) -> float {
        return (j >= 0 && j < KF) ? Hb[(size_t)j * HW + p] : 0.0f;
    };

    // ---- single patch fill for this CTA's channel ----
    {
        const float* src = inp + ((size_t)(b * CC + c) * IN_H + y0) * IN_W + x0;
        for (int t = tid; t < PATCH_H * (PATCH_W / 2); t += NTHREADS) {
            int r  = t / (PATCH_W / 2);
            int c2 = t - r * (PATCH_W / 2);
            float2 v = *(const float2*)(src + (size_t)r * IN_W + 2 * c2);
            *(float2*)(&sm[r][2 * c2]) = v;
        }
    }

    float res0, res1, res2, res3;

    // ================= PHASE A : pairs k = 0..13 (taps j <= 28) =============
    {
        uint64_t wa0[14], wa1[14], wa2[13], wa3[13];
#pragma unroll
        for (int k = 0; k < 14; ++k) {
            wa0[k] = pk2(hz(0, 2 * k),     hz(0, 2 * k + 1));
            wa1[k] = pk2(hz(1, 2 * k - 1), hz(1, 2 * k));
        }
#pragma unroll
        for (int k = 1; k < 14; ++k) {
            wa2[k - 1] = pk2(hz(2, 2 * k - 2), hz(2, 2 * k - 1));
            wa3[k - 1] = pk2(hz(3, 2 * k - 3), hz(3, 2 * k - 2));
        }

        __syncthreads();   // patch visible before compute

        uint64_t o0 = 0, o1 = 0, o2 = 0, o3 = 0;
#pragma unroll 1
        for (int i = 0; i < KF; ++i) {
            float4 v4 = *(const float4*)(Vb + (size_t)i * HW);
            const float4* srow4 = (const float4*)(&sm[wy + i][0]);
            uint64_t a0 = 0, a1 = 0, a2 = 0, a3 = 0;
#pragma unroll
            for (int t = 0; t < 7; ++t) {
                float4 s4 = srow4[lane + t];
                uint64_t q0 = pk2(s4.x, s4.y);   // pair k = 2t
                uint64_t q1 = pk2(s4.z, s4.w);   // pair k = 2t+1
                int k0 = 2 * t, k1 = 2 * t + 1;
                ffma2(a0, wa0[k0], q0);
                ffma2(a1, wa1[k0], q0);
                if (k0 >= 1) { ffma2(a2, wa2[k0 - 1], q0); ffma2(a3, wa3[k0 - 1], q0); }
                ffma2(a0, wa0[k1], q1);
                ffma2(a1, wa1[k1], q1);
                ffma2(a2, wa2[k1 - 1], q1);
                ffma2(a3, wa3[k1 - 1], q1);
            }
            ffma2(o0, pk2(v4.x, v4.x), a0);
            ffma2(o1, pk2(v4.y, v4.y), a1);
            ffma2(o2, pk2(v4.z, v4.z), a2);
            ffma2(o3, pk2(v4.w, v4.w), a3);
        }
        res0 = hadd2(o0);
        res1 = hadd2(o1);
        res2 = hadd2(o2);
        res3 = hadd2(o3);
    }

    __syncthreads();   // fence: keep phase-B weight loads below phase A

    // ================= PHASE B : pairs k = 14..26 (taps j >= 25) ============
    {
        uint64_t wb0[12], wb1[12], wb2[13], wb3[13];
#pragma unroll
        for (int k = 14; k < 26; ++k) {
            wb0[k - 14] = pk2(hz(0, 2 * k),     hz(0, 2 * k + 1)); // k=25 -> pad
            wb1[k - 14] = pk2(hz(1, 2 * k - 1), hz(1, 2 * k));
        }
#pragma unroll
        for (int k = 14; k < 27; ++k) {
            wb2[k - 14] = pk2(hz(2, 2 * k - 2), hz(2, 2 * k - 1)); // k=26 -> pad
            wb3[k - 14] = pk2(hz(3, 2 * k - 3), hz(3, 2 * k - 2));
        }

        uint64_t o0 = 0, o1 = 0, o2 = 0, o3 = 0;
#pragma unroll 1
        for (int i = 0; i < KF; ++i) {
            float4 v4 = *(const float4*)(Vb + (size_t)i * HW);
            const float* srow = &sm[wy + i][0];
            const float4* srow4 = (const float4*)srow;
            uint64_t a0 = 0, a1 = 0, a2 = 0, a3 = 0;
#pragma unroll
            for (int t = 0; t < 6; ++t) {
                float4 s4 = srow4[lane + 7 + t];          // floats 28..51
                uint64_t q0 = pk2(s4.x, s4.y);            // pair k = 14+2t
                uint64_t q1 = pk2(s4.z, s4.w);            // pair k = 15+2t
                int k0 = 2 * t, k1 = 2 * t + 1;           // rel index
                ffma2(a0, wb0[k0], q0);
                ffma2(a1, wb1[k0], q0);
                ffma2(a2, wb2[k0], q0);
                ffma2(a3, wb3[k0], q0);
                ffma2(a0, wb0[k1], q1);
                ffma2(a1, wb1[k1], q1);
                ffma2(a2, wb2[k1], q1);
                ffma2(a3, wb3[k1], q1);
            }
            {   // tail pair k = 26 (floats 52,53): pixels 2,3 only
                float2 s2 = *(const float2*)(srow + 4 * lane + 52);
                uint64_t q = pk2(s2.x, s2.y);
                ffma2(a2, wb2[12], q);
                ffma2(a3, wb3[12], q);
            }
            ffma2(o0, pk2(v4.x, v4.x), a0);
            ffma2(o1, pk2(v4.y, v4.y), a1);
            ffma2(o2, pk2(v4.z, v4.z), a2);
            ffma2(o3, pk2(v4.w, v4.w), a3);
        }
        res0 += hadd2(o0);
        res1 += hadd2(o1);
        res2 += hadd2(o2);
        res3 += hadd2(o3);
    }

    // ---- write out ----
    float* o = out + ((size_t)(b * CC + c) * HH + y) * WW + w0;
    *(float4*)o = make_float4(res0, res1, res2, res3);
}

extern "C" void kernel_launch(void* const* d_in, const int* in_sizes, int n_in,
                              void* d_out, int out_size)
{
    (void)in_sizes; (void)n_in; (void)out_size;
    const float* inp = (const float*)d_in[0];   // [B, C, 306, 306]
    const float* ver = (const float*)d_in[1];   // [B, 51, 256, 256]
    const float* hor = (const float*)d_in[2];   // [B, 51, 256, 256]
    float*       out = (float*)d_out;           // [B, C, 256, 256]

    dim3 grid(WW / TILE_W, HH / TILE_H, BB * CC);   // (2, 64, 6) = 768 blocks
    dim3 block(NTHREADS);
    sepconv_kernel<<<grid, block>>>(inp, ver, hor, out);
}